// round 5
// baseline (speedup 1.0000x reference)
#include <cuda_runtime.h>
#include <cuda_bf16.h>
#include <math.h>
#include <stdint.h>

// Problem dims (fixed by the dataset)
#define B_  4
#define T_  4096
#define D_  1024
#define R_  128
#define DFF_ 4096
#define BT_ (B_ * T_)   // 16384

// ---------------------------------------------------------------------------
// Scratch (device globals; allocation-free)
// ---------------------------------------------------------------------------
__device__ float g_normed[(size_t)BT_ * D_];   // 64 MB
__device__ float g_q[(size_t)BT_ * R_];
__device__ float g_k[(size_t)BT_ * R_];
__device__ float g_v[(size_t)BT_ * R_];
__device__ float g_y[(size_t)BT_ * R_];
__device__ float g_h[(size_t)BT_ * D_];        // 64 MB
__device__ float g_t1[(size_t)BT_ * DFF_];     // 256 MB
// tf32-rounded weights
__device__ float g_wq[(size_t)R_ * D_];
__device__ float g_wk[(size_t)R_ * D_];
__device__ float g_wv[(size_t)R_ * D_];
__device__ float g_wo[(size_t)D_ * R_];
__device__ float g_w1[(size_t)DFF_ * D_];
__device__ float g_w3[(size_t)DFF_ * D_];
__device__ float g_w2[(size_t)D_ * DFF_];

// ---------------------------------------------------------------------------
// Helpers
// ---------------------------------------------------------------------------
__device__ __forceinline__ uint32_t tf32_bits(float x) {
    uint32_t u;
    asm("cvt.rna.tf32.f32 %0, %1;" : "=r"(u) : "f"(x));
    return u;
}
__device__ __forceinline__ float tf32f(float x) { return __uint_as_float(tf32_bits(x)); }

__device__ __forceinline__ void mma_tf32(float& c0, float& c1, float& c2, float& c3,
                                         uint32_t a0, uint32_t a1, uint32_t a2, uint32_t a3,
                                         uint32_t b0, uint32_t b1) {
    asm volatile(
        "mma.sync.aligned.m16n8k8.row.col.f32.tf32.tf32.f32 "
        "{%0,%1,%2,%3}, {%4,%5,%6,%7}, {%8,%9}, {%0,%1,%2,%3};\n"
        : "+f"(c0), "+f"(c1), "+f"(c2), "+f"(c3)
        : "r"(a0), "r"(a1), "r"(a2), "r"(a3), "r"(b0), "r"(b1));
}

__device__ __forceinline__ void cp_async16(void* smem, const void* gmem) {
    uint32_t s = (uint32_t)__cvta_generic_to_shared(smem);
    asm volatile("cp.async.ca.shared.global [%0], [%1], 16;\n" :: "r"(s), "l"(gmem));
}
__device__ __forceinline__ void cp_commit() { asm volatile("cp.async.commit_group;\n" ::: "memory"); }
__device__ __forceinline__ void cp_wait0()  { asm volatile("cp.async.wait_group 0;\n" ::: "memory"); }
__device__ __forceinline__ void cp_wait1()  { asm volatile("cp.async.wait_group 1;\n" ::: "memory"); }

// ---------------------------------------------------------------------------
// tf32 rounding prep for weights
// ---------------------------------------------------------------------------
__global__ void __launch_bounds__(256) round4_kernel(const float4* __restrict__ in,
                                                     float4* __restrict__ out, int n4) {
    int i = blockIdx.x * 256 + threadIdx.x;
    if (i < n4) {
        float4 v = in[i];
        out[i] = make_float4(tf32f(v.x), tf32f(v.y), tf32f(v.z), tf32f(v.w));
    }
}

// ---------------------------------------------------------------------------
// RMSNorm: one block per row of D_=1024; output rounded to tf32
// ---------------------------------------------------------------------------
__global__ void __launch_bounds__(256) rmsnorm_kernel(const float* __restrict__ x,
                                                      const float* __restrict__ w,
                                                      float* __restrict__ out) {
    const size_t row = blockIdx.x;
    const float* xr = x + row * D_;
    float s = 0.f;
    for (int i = threadIdx.x; i < D_; i += 256) {
        float v = xr[i];
        s += v * v;
    }
    __shared__ float red[256];
    red[threadIdx.x] = s;
    __syncthreads();
    for (int off = 128; off > 0; off >>= 1) {
        if (threadIdx.x < off) red[threadIdx.x] += red[threadIdx.x + off];
        __syncthreads();
    }
    const float rms = rsqrtf(red[0] / (float)D_ + 1e-6f);
    float* orow = out + row * D_;
    for (int i = threadIdx.x; i < D_; i += 256) {
        orow[i] = tf32f(xr[i] * rms * w[i]);
    }
}

// ---------------------------------------------------------------------------
// Big-tile TF32 GEMM: C[M,N] = A[M,K] @ B[N,K]^T  (+ epilogue)
// CTA tile 128x256, warp tile 64x64 (8 warps in 2x4), BK=16, 3-stage cp.async.
//   MODE 0: C = acc
//   MODE 1: C = X + acc
//   MODE 2: C = tf32(X * silu(acc))   (X may alias C)
// Requires M%128==0, N%256==0, K%16==0.
// ---------------------------------------------------------------------------
#define GPAD 20
#define BIG_AS_FLOATS (128 * GPAD)
#define BIG_BS_FLOATS (256 * GPAD)
#define BIG_STAGE_FLOATS (BIG_AS_FLOATS + BIG_BS_FLOATS)
#define BIG_SMEM_BYTES (3 * BIG_STAGE_FLOATS * 4)   // 92160

template <int MODE>
__global__ void __launch_bounds__(256) big_gemm(const float* __restrict__ A,
                                                const float* __restrict__ Bm,
                                                const float* __restrict__ X,
                                                float* __restrict__ C,
                                                int M, int N, int K) {
    extern __shared__ __align__(16) float smem[];

    const int tid  = threadIdx.x;
    const int lane = tid & 31;
    const int wid  = tid >> 5;
    const int wr   = (wid >> 2) * 64;   // warp row base: 0 or 64
    const int wc   = (wid & 3) * 64;    // warp col base: 0,64,128,192
    const int gm   = lane >> 2;         // 0..7
    const int kq   = lane & 3;          // 0..3

    const int bm = blockIdx.y * 128;
    const int bn = blockIdx.x * 256;

    // loaders: A 512 float4 (2/thread), B 1024 float4 (4/thread)
    const int lrA  = tid >> 2;          // 0..63
    const int lc4  = (tid & 3) * 4;     // 0,4,8,12
    const float* Aptr = A + (size_t)(bm + lrA) * K + lc4;
    const float* Bptr = Bm + (size_t)(bn + lrA) * K + lc4;
    const size_t s64 = (size_t)64 * K;

    float acc[4][8][4];
#pragma unroll
    for (int mi = 0; mi < 4; mi++)
#pragma unroll
        for (int ni = 0; ni < 8; ni++)
#pragma unroll
            for (int r = 0; r < 4; r++) acc[mi][ni][r] = 0.f;

    const int NT = K >> 4;

    // stage loader
    auto load_stage = [&](int stage_idx, int k0) {
        float* As = smem + (stage_idx) * BIG_STAGE_FLOATS;
        float* Bs = As + BIG_AS_FLOATS;
        const float* Ap = Aptr + k0;
        const float* Bp = Bptr + k0;
        cp_async16(&As[lrA * GPAD + lc4], Ap);
        cp_async16(&As[(lrA + 64) * GPAD + lc4], Ap + s64);
        cp_async16(&Bs[lrA * GPAD + lc4], Bp);
        cp_async16(&Bs[(lrA + 64) * GPAD + lc4], Bp + s64);
        cp_async16(&Bs[(lrA + 128) * GPAD + lc4], Bp + 2 * s64);
        cp_async16(&Bs[(lrA + 192) * GPAD + lc4], Bp + 3 * s64);
        cp_commit();
    };

    load_stage(0, 0);
    if (NT > 1) load_stage(1, 16);

    for (int it = 0; it < NT; it++) {
        if (it + 1 < NT) cp_wait1(); else cp_wait0();
        __syncthreads();

        const int buf = it % 3;
        if (it + 2 < NT) load_stage((it + 2) % 3, (it + 2) * 16);

        const float* As = smem + buf * BIG_STAGE_FLOATS;
        const float* Bs = As + BIG_AS_FLOATS;

#pragma unroll
        for (int ks = 0; ks < 2; ks++) {
            const int kb = ks * 8;
            uint32_t af[4][4], bf[8][2];
#pragma unroll
            for (int mi = 0; mi < 4; mi++) {
                const int m0 = wr + mi * 16 + gm;
                af[mi][0] = __float_as_uint(As[m0 * GPAD + kb + kq]);
                af[mi][1] = __float_as_uint(As[(m0 + 8) * GPAD + kb + kq]);
                af[mi][2] = __float_as_uint(As[m0 * GPAD + kb + kq + 4]);
                af[mi][3] = __float_as_uint(As[(m0 + 8) * GPAD + kb + kq + 4]);
            }
#pragma unroll
            for (int ni = 0; ni < 8; ni++) {
                const int n0 = wc + ni * 8 + gm;
                bf[ni][0] = __float_as_uint(Bs[n0 * GPAD + kb + kq]);
                bf[ni][1] = __float_as_uint(Bs[n0 * GPAD + kb + kq + 4]);
            }
#pragma unroll
            for (int mi = 0; mi < 4; mi++)
#pragma unroll
                for (int ni = 0; ni < 8; ni++)
                    mma_tf32(acc[mi][ni][0], acc[mi][ni][1], acc[mi][ni][2], acc[mi][ni][3],
                             af[mi][0], af[mi][1], af[mi][2], af[mi][3],
                             bf[ni][0], bf[ni][1]);
        }
        __syncthreads();
    }

    // epilogue
#pragma unroll
    for (int mi = 0; mi < 4; mi++) {
        const int r0 = bm + wr + mi * 16 + gm;
        const int r1 = r0 + 8;
#pragma unroll
        for (int ni = 0; ni < 8; ni++) {
            const int c = bn + wc + ni * 8 + 2 * kq;
            const size_t o0 = (size_t)r0 * N + c;
            const size_t o1 = (size_t)r1 * N + c;
            float2 v0 = make_float2(acc[mi][ni][0], acc[mi][ni][1]);
            float2 v1 = make_float2(acc[mi][ni][2], acc[mi][ni][3]);
            if (MODE == 1) {
                float2 x0 = *(const float2*)(&X[o0]);
                float2 x1 = *(const float2*)(&X[o1]);
                v0.x += x0.x; v0.y += x0.y;
                v1.x += x1.x; v1.y += x1.y;
            } else if (MODE == 2) {
                float2 x0 = *(const float2*)(&X[o0]);
                float2 x1 = *(const float2*)(&X[o1]);
                v0.x = tf32f(x0.x * (v0.x / (1.f + expf(-v0.x))));
                v0.y = tf32f(x0.y * (v0.y / (1.f + expf(-v0.y))));
                v1.x = tf32f(x1.x * (v1.x / (1.f + expf(-v1.x))));
                v1.y = tf32f(x1.y * (v1.y / (1.f + expf(-v1.y))));
            }
            *(float2*)(&C[o0]) = v0;
            *(float2*)(&C[o1]) = v1;
        }
    }
}

// ---------------------------------------------------------------------------
// 128x128 TF32 GEMM (QKV / Wo path), 2-stage cp.async, warp tile 64x32.
// ---------------------------------------------------------------------------
template <int MODE>
__device__ __forceinline__ void run_gemm(const float* __restrict__ A,
                                         const float* __restrict__ Bm,
                                         const float* __restrict__ X,
                                         float* __restrict__ C,
                                         int M, int N, int K, int bm, int bn) {
    __shared__ __align__(16) float As[2][128][GPAD];
    __shared__ __align__(16) float Bs[2][128][GPAD];

    const int tid  = threadIdx.x;
    const int lane = tid & 31;
    const int wid  = tid >> 5;
    const int wr   = (wid >> 2) * 64;
    const int wc   = (wid & 3) * 32;
    const int gm   = lane >> 2;
    const int kq   = lane & 3;

    const int lr  = tid >> 2;
    const int lc4 = (tid & 3) * 4;

    const float* Aptr = A + (size_t)(bm + lr) * K + lc4;
    const float* Bptr = Bm + (size_t)(bn + lr) * K + lc4;
    const size_t s64 = (size_t)64 * K;

    float acc[4][4][4];
#pragma unroll
    for (int mi = 0; mi < 4; mi++)
#pragma unroll
        for (int ni = 0; ni < 4; ni++)
#pragma unroll
            for (int r = 0; r < 4; r++) acc[mi][ni][r] = 0.f;

    cp_async16(&As[0][lr][lc4], Aptr);
    cp_async16(&As[0][lr + 64][lc4], Aptr + s64);
    cp_async16(&Bs[0][lr][lc4], Bptr);
    cp_async16(&Bs[0][lr + 64][lc4], Bptr + s64);
    cp_commit();

    const int NT = K >> 4;
    int buf = 0;
    for (int it = 0; it < NT; it++) {
        if (it + 1 < NT) {
            const float* Ap = Aptr + (size_t)(it + 1) * 16;
            const float* Bp = Bptr + (size_t)(it + 1) * 16;
            const int nb = buf ^ 1;
            cp_async16(&As[nb][lr][lc4], Ap);
            cp_async16(&As[nb][lr + 64][lc4], Ap + s64);
            cp_async16(&Bs[nb][lr][lc4], Bp);
            cp_async16(&Bs[nb][lr + 64][lc4], Bp + s64);
            cp_commit();
            cp_wait1();
        } else {
            cp_wait0();
        }
        __syncthreads();

#pragma unroll
        for (int ks = 0; ks < 2; ks++) {
            const int kb = ks * 8;
            uint32_t af[4][4], bf[4][2];
#pragma unroll
            for (int mi = 0; mi < 4; mi++) {
                const int m0 = wr + mi * 16 + gm;
                af[mi][0] = __float_as_uint(As[buf][m0][kb + kq]);
                af[mi][1] = __float_as_uint(As[buf][m0 + 8][kb + kq]);
                af[mi][2] = __float_as_uint(As[buf][m0][kb + kq + 4]);
                af[mi][3] = __float_as_uint(As[buf][m0 + 8][kb + kq + 4]);
            }
#pragma unroll
            for (int ni = 0; ni < 4; ni++) {
                const int n0 = wc + ni * 8 + gm;
                bf[ni][0] = __float_as_uint(Bs[buf][n0][kb + kq]);
                bf[ni][1] = __float_as_uint(Bs[buf][n0][kb + kq + 4]);
            }
#pragma unroll
            for (int mi = 0; mi < 4; mi++)
#pragma unroll
                for (int ni = 0; ni < 4; ni++)
                    mma_tf32(acc[mi][ni][0], acc[mi][ni][1], acc[mi][ni][2], acc[mi][ni][3],
                             af[mi][0], af[mi][1], af[mi][2], af[mi][3],
                             bf[ni][0], bf[ni][1]);
        }
        __syncthreads();
        buf ^= 1;
    }

#pragma unroll
    for (int mi = 0; mi < 4; mi++) {
        const int r0 = bm + wr + mi * 16 + gm;
        const int r1 = r0 + 8;
#pragma unroll
        for (int ni = 0; ni < 4; ni++) {
            const int c = bn + wc + ni * 8 + 2 * kq;
            const size_t o0 = (size_t)r0 * N + c;
            const size_t o1 = (size_t)r1 * N + c;
            float2 v0 = make_float2(acc[mi][ni][0], acc[mi][ni][1]);
            float2 v1 = make_float2(acc[mi][ni][2], acc[mi][ni][3]);
            if (MODE == 1) {
                float2 x0 = *(const float2*)(&X[o0]);
                float2 x1 = *(const float2*)(&X[o1]);
                v0.x += x0.x; v0.y += x0.y;
                v1.x += x1.x; v1.y += x1.y;
            }
            *(float2*)(&C[o0]) = v0;
            *(float2*)(&C[o1]) = v1;
        }
    }
}

template <int MODE>
__global__ void __launch_bounds__(256, 2) tfgemm_kernel(const float* __restrict__ A,
                                                        const float* __restrict__ Bm,
                                                        const float* __restrict__ X,
                                                        float* __restrict__ C,
                                                        int M, int N, int K) {
    run_gemm<MODE>(A, Bm, X, C, M, N, K, blockIdx.y * 128, blockIdx.x * 128);
}

__global__ void __launch_bounds__(256, 2) qkv_kernel(const float* __restrict__ A,
                                                     const float* __restrict__ Bq,
                                                     const float* __restrict__ Bk,
                                                     const float* __restrict__ Bv,
                                                     float* __restrict__ Cq,
                                                     float* __restrict__ Ck,
                                                     float* __restrict__ Cv,
                                                     int M, int K) {
    const float* Bm = (blockIdx.x == 0) ? Bq : (blockIdx.x == 1) ? Bk : Bv;
    float* C = (blockIdx.x == 0) ? Cq : (blockIdx.x == 1) ? Ck : Cv;
    run_gemm<0>(A, Bm, nullptr, C, M, R_, K, blockIdx.y * 128, 0);
}

// ---------------------------------------------------------------------------
// RoPE (in-place on q and k)
// ---------------------------------------------------------------------------
__global__ void __launch_bounds__(64) rope_kernel(float* __restrict__ q,
                                                  float* __restrict__ k,
                                                  const float* __restrict__ cosp,
                                                  const float* __restrict__ sinp) {
    const int bt = blockIdx.x;
    const int j = threadIdx.x;
    const int t = bt & (T_ - 1);
    const float c = cosp[t * 64 + j];
    const float s = sinp[t * 64 + j];
    const size_t base = (size_t)bt * R_;

    float q1 = q[base + j], q2 = q[base + 64 + j];
    q[base + j]      = q1 * c + q2 * s;
    q[base + 64 + j] = q2 * c - q1 * s;

    float k1 = k[base + j], k2 = k[base + 64 + j];
    k[base + j]      = k1 * c + k2 * s;
    k[base + 64 + j] = k2 * c - k1 * s;
}

// ---------------------------------------------------------------------------
// Sliding-window causal attention, flash-style online softmax.
// ---------------------------------------------------------------------------
#define ATTN_SMEM_FLOATS (32 * 128 + 32 * 128 + 64 * 132)
#define ATTN_SMEM_BYTES (ATTN_SMEM_FLOATS * 4)

__global__ void __launch_bounds__(64) attn_kernel(const float* __restrict__ q,
                                                  const float* __restrict__ k,
                                                  const float* __restrict__ v,
                                                  float* __restrict__ y,
                                                  const int* __restrict__ win_ptr) {
    extern __shared__ float sm[];
    float* k_s = sm;
    float* v_s = k_s + 32 * 128;
    float* O_s = v_s + 32 * 128;

    const int b = blockIdx.y;
    const int t0 = blockIdx.x * 64;
    const int tid = threadIdx.x;
    const int W = win_ptr[0];
    const float scale = rsqrtf((float)R_);
    const size_t qbase = ((size_t)b * T_ + t0) * R_;

    float4 qr[32];
    {
        const float4* qp = (const float4*)(q + qbase + (size_t)tid * R_);
#pragma unroll
        for (int i = 0; i < 32; i++) {
            float4 t = qp[i];
            qr[i] = make_float4(t.x * scale, t.y * scale, t.z * scale, t.w * scale);
        }
    }
    {
        float4 z = make_float4(0.f, 0.f, 0.f, 0.f);
        float4* Or4 = (float4*)(O_s + tid * 132);
#pragma unroll
        for (int d4 = 0; d4 < 32; d4++) Or4[d4] = z;
    }
    __syncthreads();

    const int t = t0 + tid;
    float m = -1e30f, l = 0.f;

    int s_lo = t0 - W;
    if (s_lo < 0) s_lo = 0;
    const int s_start = s_lo & ~31;

    for (int s0 = s_start; s0 < t0 + 64; s0 += 32) {
        {
            const float4* kp = (const float4*)(k + ((size_t)b * T_ + s0) * R_);
            const float4* vp = (const float4*)(v + ((size_t)b * T_ + s0) * R_);
            float4* ks4 = (float4*)k_s;
            float4* vs4 = (float4*)v_s;
#pragma unroll
            for (int i = 0; i < 16; i++) {
                ks4[tid + i * 64] = kp[tid + i * 64];
                vs4[tid + i * 64] = vp[tid + i * 64];
            }
        }
        __syncthreads();

        float p[32];
        float mt = m;
#pragma unroll 4
        for (int j = 0; j < 32; j++) {
            const float4* kr = (const float4*)(k_s + j * 128);
            float4 s4 = make_float4(0.f, 0.f, 0.f, 0.f);
#pragma unroll
            for (int d4 = 0; d4 < 32; d4++) {
                float4 kv = kr[d4];
                s4.x += qr[d4].x * kv.x;
                s4.y += qr[d4].y * kv.y;
                s4.z += qr[d4].z * kv.z;
                s4.w += qr[d4].w * kv.w;
            }
            float s = (s4.x + s4.y) + (s4.z + s4.w);
            const int sidx = s0 + j;
            if (sidx > t || (t - sidx) > W) s = -1e30f;
            p[j] = s;
            mt = fmaxf(mt, s);
        }

        const float alpha = expf(m - mt);
        m = mt;
        float lt = 0.f;
#pragma unroll
        for (int j = 0; j < 32; j++) {
            const float pv = (p[j] > -1e29f) ? expf(p[j] - mt) : 0.f;
            p[j] = pv;
            lt += pv;
        }
        l = l * alpha + lt;

        float4* Or4 = (float4*)(O_s + tid * 132);
        const float4* vs4 = (const float4*)v_s;
#pragma unroll 2
        for (int d4 = 0; d4 < 32; d4++) {
            float4 acc = Or4[d4];
            acc.x *= alpha; acc.y *= alpha; acc.z *= alpha; acc.w *= alpha;
#pragma unroll
            for (int j = 0; j < 32; j++) {
                float4 vv = vs4[j * 32 + d4];
                acc.x += p[j] * vv.x;
                acc.y += p[j] * vv.y;
                acc.z += p[j] * vv.z;
                acc.w += p[j] * vv.w;
            }
            Or4[d4] = acc;
        }
        __syncthreads();
    }

    const float inv_l = 1.f / l;
    float4* yo = (float4*)(y + qbase + (size_t)tid * R_);
    const float4* Or4 = (const float4*)(O_s + tid * 132);
#pragma unroll
    for (int d4 = 0; d4 < 32; d4++) {
        float4 o = Or4[d4];
        yo[d4] = make_float4(tf32f(o.x * inv_l), tf32f(o.y * inv_l),
                             tf32f(o.z * inv_l), tf32f(o.w * inv_l));
    }
}

// ---------------------------------------------------------------------------
// Host launcher
// ---------------------------------------------------------------------------
extern "C" void kernel_launch(void* const* d_in, const int* in_sizes, int n_in,
                              void* d_out, int out_size) {
    const float* x    = (const float*)d_in[0];
    const float* Uq   = (const float*)d_in[1];
    const float* Uk   = (const float*)d_in[2];
    const float* Uv   = (const float*)d_in[3];
    const float* cosp = (const float*)d_in[4];
    const float* sinp = (const float*)d_in[5];
    const float* ln1w = (const float*)d_in[6];
    const float* ln2w = (const float*)d_in[7];
    const float* Wo   = (const float*)d_in[8];
    const float* w1   = (const float*)d_in[9];
    const float* w3   = (const float*)d_in[10];
    const float* w2   = (const float*)d_in[11];
    const int*   win  = (const int*)d_in[12];
    float* out = (float*)d_out;

    float *normed, *q, *k, *v, *y, *h, *t1;
    float *wq, *wk, *wv, *wo, *w1r, *w3r, *w2r;
    cudaGetSymbolAddress((void**)&normed, g_normed);
    cudaGetSymbolAddress((void**)&q, g_q);
    cudaGetSymbolAddress((void**)&k, g_k);
    cudaGetSymbolAddress((void**)&v, g_v);
    cudaGetSymbolAddress((void**)&y, g_y);
    cudaGetSymbolAddress((void**)&h, g_h);
    cudaGetSymbolAddress((void**)&t1, g_t1);
    cudaGetSymbolAddress((void**)&wq, g_wq);
    cudaGetSymbolAddress((void**)&wk, g_wk);
    cudaGetSymbolAddress((void**)&wv, g_wv);
    cudaGetSymbolAddress((void**)&wo, g_wo);
    cudaGetSymbolAddress((void**)&w1r, g_w1);
    cudaGetSymbolAddress((void**)&w3r, g_w3);
    cudaGetSymbolAddress((void**)&w2r, g_w2);

    cudaFuncSetAttribute(attn_kernel, cudaFuncAttributeMaxDynamicSharedMemorySize,
                         ATTN_SMEM_BYTES);
    cudaFuncSetAttribute(big_gemm<0>, cudaFuncAttributeMaxDynamicSharedMemorySize, BIG_SMEM_BYTES);
    cudaFuncSetAttribute(big_gemm<1>, cudaFuncAttributeMaxDynamicSharedMemorySize, BIG_SMEM_BYTES);
    cudaFuncSetAttribute(big_gemm<2>, cudaFuncAttributeMaxDynamicSharedMemorySize, BIG_SMEM_BYTES);

    // weight prep (tf32 rounding)
    const int nSmall = R_ * D_ / 4;
    const int nBig   = DFF_ * D_ / 4;
    round4_kernel<<<(nSmall + 255) / 256, 256>>>((const float4*)Uq, (float4*)wq, nSmall);
    round4_kernel<<<(nSmall + 255) / 256, 256>>>((const float4*)Uk, (float4*)wk, nSmall);
    round4_kernel<<<(nSmall + 255) / 256, 256>>>((const float4*)Uv, (float4*)wv, nSmall);
    round4_kernel<<<(nSmall + 255) / 256, 256>>>((const float4*)Wo, (float4*)wo, nSmall);
    round4_kernel<<<(nBig + 255) / 256, 256>>>((const float4*)w1, (float4*)w1r, nBig);
    round4_kernel<<<(nBig + 255) / 256, 256>>>((const float4*)w3, (float4*)w3r, nBig);
    round4_kernel<<<(nBig + 255) / 256, 256>>>((const float4*)w2, (float4*)w2r, nBig);

    // 1) normed = tf32(rmsnorm(x, ln1_w))
    rmsnorm_kernel<<<BT_, 256>>>(x, ln1w, normed);

    // 2) fused q,k,v projections
    qkv_kernel<<<dim3(3, BT_ / 128), 256>>>(normed, wq, wk, wv, q, k, v, BT_, D_);

    // 3) RoPE
    rope_kernel<<<BT_, 64>>>(q, k, cosp, sinp);

    // 4) attention -> y (tf32-rounded)
    attn_kernel<<<dim3(T_ / 64, B_), 64, ATTN_SMEM_BYTES>>>(q, k, v, y, win);

    // 5) out = x + y @ Wo^T
    tfgemm_kernel<1><<<dim3(D_ / 128, BT_ / 128), 256>>>(y, wo, x, out, BT_, D_, R_);

    // 6) h = tf32(rmsnorm(out, ln2_w))
    rmsnorm_kernel<<<BT_, 256>>>(out, ln2w, h);

    // 7) t1 = h @ w1^T   (big tile)
    big_gemm<0><<<dim3(DFF_ / 256, BT_ / 128), 256, BIG_SMEM_BYTES>>>(
        h, w1r, nullptr, t1, BT_, DFF_, D_);

    // 8) t1 = tf32(t1 * silu(h @ w3^T))   (big tile)
    big_gemm<2><<<dim3(DFF_ / 256, BT_ / 128), 256, BIG_SMEM_BYTES>>>(
        h, w3r, t1, t1, BT_, DFF_, D_);

    // 9) out = out + t1 @ w2^T   (big tile)
    big_gemm<1><<<dim3(D_ / 256, BT_ / 128), 256, BIG_SMEM_BYTES>>>(
        t1, w2r, out, out, BT_, D_, DFF_);
}

// round 7
// speedup vs baseline: 1.3874x; 1.3874x over previous
#include <cuda_runtime.h>
#include <cuda_bf16.h>
#include <math.h>
#include <stdint.h>

// Problem dims (fixed by the dataset)
#define B_  4
#define T_  4096
#define D_  1024
#define R_  128
#define DFF_ 4096
#define BT_ (B_ * T_)   // 16384

// ---------------------------------------------------------------------------
// Scratch (device globals; allocation-free)
// ---------------------------------------------------------------------------
__device__ float g_normed[(size_t)BT_ * D_];   // 64 MB
__device__ float g_q[(size_t)BT_ * R_];
__device__ float g_k[(size_t)BT_ * R_];
__device__ float g_v[(size_t)BT_ * R_];
__device__ float g_y[(size_t)BT_ * R_];
__device__ float g_h[(size_t)BT_ * D_];        // 64 MB
__device__ float g_t1[(size_t)BT_ * DFF_];     // 256 MB
// tf32-rounded weights
__device__ float g_wq[(size_t)R_ * D_];
__device__ float g_wk[(size_t)R_ * D_];
__device__ float g_wv[(size_t)R_ * D_];
__device__ float g_wo[(size_t)D_ * R_];
__device__ float g_w1[(size_t)DFF_ * D_];
__device__ float g_w3[(size_t)DFF_ * D_];
__device__ float g_w2[(size_t)D_ * DFF_];

// ---------------------------------------------------------------------------
// Helpers
// ---------------------------------------------------------------------------
__device__ __forceinline__ uint32_t tf32_bits(float x) {
    uint32_t u;
    asm("cvt.rna.tf32.f32 %0, %1;" : "=r"(u) : "f"(x));
    return u;
}
__device__ __forceinline__ float tf32f(float x) { return __uint_as_float(tf32_bits(x)); }

__device__ __forceinline__ void mma_tf32(float& c0, float& c1, float& c2, float& c3,
                                         uint32_t a0, uint32_t a1, uint32_t a2, uint32_t a3,
                                         uint32_t b0, uint32_t b1) {
    asm volatile(
        "mma.sync.aligned.m16n8k8.row.col.f32.tf32.tf32.f32 "
        "{%0,%1,%2,%3}, {%4,%5,%6,%7}, {%8,%9}, {%0,%1,%2,%3};\n"
        : "+f"(c0), "+f"(c1), "+f"(c2), "+f"(c3)
        : "r"(a0), "r"(a1), "r"(a2), "r"(a3), "r"(b0), "r"(b1));
}

__device__ __forceinline__ void cp_async16(void* smem, const void* gmem) {
    uint32_t s = (uint32_t)__cvta_generic_to_shared(smem);
    asm volatile("cp.async.ca.shared.global [%0], [%1], 16;\n" :: "r"(s), "l"(gmem));
}
__device__ __forceinline__ void cp_commit() { asm volatile("cp.async.commit_group;\n" ::: "memory"); }
__device__ __forceinline__ void cp_wait0()  { asm volatile("cp.async.wait_group 0;\n" ::: "memory"); }
__device__ __forceinline__ void cp_wait1()  { asm volatile("cp.async.wait_group 1;\n" ::: "memory"); }

// ---------------------------------------------------------------------------
// tf32 rounding prep for weights
// ---------------------------------------------------------------------------
__global__ void __launch_bounds__(256) round4_kernel(const float4* __restrict__ in,
                                                     float4* __restrict__ out, int n4) {
    int i = blockIdx.x * 256 + threadIdx.x;
    if (i < n4) {
        float4 v = in[i];
        out[i] = make_float4(tf32f(v.x), tf32f(v.y), tf32f(v.z), tf32f(v.w));
    }
}

// ---------------------------------------------------------------------------
// RMSNorm: one block per row of D_=1024; output rounded to tf32
// ---------------------------------------------------------------------------
__global__ void __launch_bounds__(256) rmsnorm_kernel(const float* __restrict__ x,
                                                      const float* __restrict__ w,
                                                      float* __restrict__ out) {
    const size_t row = blockIdx.x;
    const float* xr = x + row * D_;
    float s = 0.f;
    for (int i = threadIdx.x; i < D_; i += 256) {
        float v = xr[i];
        s += v * v;
    }
    __shared__ float red[256];
    red[threadIdx.x] = s;
    __syncthreads();
    for (int off = 128; off > 0; off >>= 1) {
        if (threadIdx.x < off) red[threadIdx.x] += red[threadIdx.x + off];
        __syncthreads();
    }
    const float rms = rsqrtf(red[0] / (float)D_ + 1e-6f);
    float* orow = out + row * D_;
    for (int i = threadIdx.x; i < D_; i += 256) {
        orow[i] = tf32f(xr[i] * rms * w[i]);
    }
}

// ---------------------------------------------------------------------------
// TF32 tensor-core GEMM: C[M,N] = A[M,K] @ B[N,K]^T  (+ epilogue)
//   MODE 0: C = acc
//   MODE 1: C = X + acc
//   MODE 2: C = tf32(X * silu(acc))   (X may alias C)
// CTA 128x128, warp tile 64x32 (8 warps 2x4), BK=32, 2-stage cp.async
// (prefetch distance 2). Dynamic smem 73.7KB -> 2 CTAs/SM.
// Requires M%128==0, N%128==0, K%32==0 (true for all uses here).
// ---------------------------------------------------------------------------
#define GP32 36
#define TILE_FLOATS (128 * GP32)
#define GEMM_SMEM_BYTES (4 * TILE_FLOATS * 4)   // 2 bufs x (A+B) = 73728

template <int MODE>
__device__ __forceinline__ void run_gemm(const float* __restrict__ A,
                                         const float* __restrict__ Bm,
                                         const float* __restrict__ X,
                                         float* __restrict__ C,
                                         int M, int N, int K, int bm, int bn) {
    extern __shared__ __align__(16) float dsm[];
    float* AsBase = dsm;                     // [2][128][GP32]
    float* BsBase = dsm + 2 * TILE_FLOATS;   // [2][128][GP32]

    const int tid  = threadIdx.x;
    const int lane = tid & 31;
    const int wid  = tid >> 5;
    const int wr   = (wid >> 2) * 64;   // warp row base: 0 or 64
    const int wc   = (wid & 3) * 32;    // warp col base: 0,32,64,96
    const int gm   = lane >> 2;         // 0..7
    const int kq   = lane & 3;          // 0..3

    // loaders: 8 float4 per thread per stage (4 A + 4 B)
    const int cr  = tid >> 3;           // 0..31
    const int cc4 = (tid & 7) * 4;      // 0,4,...,28

    const float* Aptr = A + (size_t)(bm + cr) * K + cc4;
    const float* Bptr = Bm + (size_t)(bn + cr) * K + cc4;
    const size_t s32 = (size_t)32 * K;

    float acc[4][4][4];
#pragma unroll
    for (int mi = 0; mi < 4; mi++)
#pragma unroll
        for (int ni = 0; ni < 4; ni++)
#pragma unroll
            for (int r = 0; r < 4; r++) acc[mi][ni][r] = 0.f;

    auto load_stage = [&](int buf, int k0) {
        float* As = AsBase + buf * TILE_FLOATS;
        float* Bs = BsBase + buf * TILE_FLOATS;
#pragma unroll
        for (int p = 0; p < 4; p++) {
            cp_async16(&As[(cr + 32 * p) * GP32 + cc4], Aptr + k0 + p * s32);
            cp_async16(&Bs[(cr + 32 * p) * GP32 + cc4], Bptr + k0 + p * s32);
        }
        cp_commit();
    };

    const int NT = K >> 5;
    load_stage(0, 0);
    if (NT > 1) load_stage(1, 32);

    for (int it = 0; it < NT; it++) {
        if (it + 1 < NT) cp_wait1(); else cp_wait0();
        __syncthreads();

        const int buf = it & 1;
        const float* As = AsBase + buf * TILE_FLOATS;
        const float* Bs = BsBase + buf * TILE_FLOATS;

#pragma unroll
        for (int ks = 0; ks < 4; ks++) {
            const int kb = ks * 8;
            uint32_t af[4][4], bf[4][2];
#pragma unroll
            for (int mi = 0; mi < 4; mi++) {
                const int m0 = (wr + mi * 16 + gm) * GP32;
                af[mi][0] = __float_as_uint(As[m0 + kb + kq]);
                af[mi][1] = __float_as_uint(As[m0 + 8 * GP32 + kb + kq]);
                af[mi][2] = __float_as_uint(As[m0 + kb + kq + 4]);
                af[mi][3] = __float_as_uint(As[m0 + 8 * GP32 + kb + kq + 4]);
            }
#pragma unroll
            for (int ni = 0; ni < 4; ni++) {
                const int n0 = (wc + ni * 8 + gm) * GP32;
                bf[ni][0] = __float_as_uint(Bs[n0 + kb + kq]);
                bf[ni][1] = __float_as_uint(Bs[n0 + kb + kq + 4]);
            }
#pragma unroll
            for (int mi = 0; mi < 4; mi++)
#pragma unroll
                for (int ni = 0; ni < 4; ni++)
                    mma_tf32(acc[mi][ni][0], acc[mi][ni][1], acc[mi][ni][2], acc[mi][ni][3],
                             af[mi][0], af[mi][1], af[mi][2], af[mi][3],
                             bf[ni][0], bf[ni][1]);
        }
        __syncthreads();
        if (it + 2 < NT) load_stage(buf, (it + 2) * 32);
    }

    // epilogue
#pragma unroll
    for (int mi = 0; mi < 4; mi++) {
        const int r0 = bm + wr + mi * 16 + gm;
        const int r1 = r0 + 8;
#pragma unroll
        for (int ni = 0; ni < 4; ni++) {
            const int c = bn + wc + ni * 8 + 2 * kq;
            const size_t o0 = (size_t)r0 * N + c;
            const size_t o1 = (size_t)r1 * N + c;
            float2 v0 = make_float2(acc[mi][ni][0], acc[mi][ni][1]);
            float2 v1 = make_float2(acc[mi][ni][2], acc[mi][ni][3]);
            if (MODE == 1) {
                float2 x0 = *(const float2*)(&X[o0]);
                float2 x1 = *(const float2*)(&X[o1]);
                v0.x += x0.x; v0.y += x0.y;
                v1.x += x1.x; v1.y += x1.y;
            } else if (MODE == 2) {
                float2 x0 = *(const float2*)(&X[o0]);
                float2 x1 = *(const float2*)(&X[o1]);
                v0.x = tf32f(x0.x * (v0.x / (1.f + expf(-v0.x))));
                v0.y = tf32f(x0.y * (v0.y / (1.f + expf(-v0.y))));
                v1.x = tf32f(x1.x * (v1.x / (1.f + expf(-v1.x))));
                v1.y = tf32f(x1.y * (v1.y / (1.f + expf(-v1.y))));
            }
            *(float2*)(&C[o0]) = v0;
            *(float2*)(&C[o1]) = v1;
        }
    }
}

template <int MODE>
__global__ void __launch_bounds__(256, 2) tfgemm_kernel(const float* __restrict__ A,
                                                        const float* __restrict__ Bm,
                                                        const float* __restrict__ X,
                                                        float* __restrict__ C,
                                                        int M, int N, int K) {
    run_gemm<MODE>(A, Bm, X, C, M, N, K, blockIdx.y * 128, blockIdx.x * 128);
}

// Fused QKV: grid (3, M/128); blockIdx.x selects weight/output
__global__ void __launch_bounds__(256, 2) qkv_kernel(const float* __restrict__ A,
                                                     const float* __restrict__ Bq,
                                                     const float* __restrict__ Bk,
                                                     const float* __restrict__ Bv,
                                                     float* __restrict__ Cq,
                                                     float* __restrict__ Ck,
                                                     float* __restrict__ Cv,
                                                     int M, int K) {
    const float* Bm = (blockIdx.x == 0) ? Bq : (blockIdx.x == 1) ? Bk : Bv;
    float* C = (blockIdx.x == 0) ? Cq : (blockIdx.x == 1) ? Ck : Cv;
    run_gemm<0>(A, Bm, nullptr, C, M, R_, K, blockIdx.y * 128, 0);
}

// ---------------------------------------------------------------------------
// RoPE (in-place on q and k)
// ---------------------------------------------------------------------------
__global__ void __launch_bounds__(64) rope_kernel(float* __restrict__ q,
                                                  float* __restrict__ k,
                                                  const float* __restrict__ cosp,
                                                  const float* __restrict__ sinp) {
    const int bt = blockIdx.x;
    const int j = threadIdx.x;
    const int t = bt & (T_ - 1);
    const float c = cosp[t * 64 + j];
    const float s = sinp[t * 64 + j];
    const size_t base = (size_t)bt * R_;

    float q1 = q[base + j], q2 = q[base + 64 + j];
    q[base + j]      = q1 * c + q2 * s;
    q[base + 64 + j] = q2 * c - q1 * s;

    float k1 = k[base + j], k2 = k[base + 64 + j];
    k[base + j]      = k1 * c + k2 * s;
    k[base + 64 + j] = k2 * c - k1 * s;
}

// ---------------------------------------------------------------------------
// Sliding-window causal attention, flash-style online softmax.
// ---------------------------------------------------------------------------
#define ATTN_SMEM_FLOATS (32 * 128 + 32 * 128 + 64 * 132)
#define ATTN_SMEM_BYTES (ATTN_SMEM_FLOATS * 4)

__global__ void __launch_bounds__(64) attn_kernel(const float* __restrict__ q,
                                                  const float* __restrict__ k,
                                                  const float* __restrict__ v,
                                                  float* __restrict__ y,
                                                  const int* __restrict__ win_ptr) {
    extern __shared__ float sm[];
    float* k_s = sm;
    float* v_s = k_s + 32 * 128;
    float* O_s = v_s + 32 * 128;

    const int b = blockIdx.y;
    const int t0 = blockIdx.x * 64;
    const int tid = threadIdx.x;
    const int W = win_ptr[0];
    const float scale = rsqrtf((float)R_);
    const size_t qbase = ((size_t)b * T_ + t0) * R_;

    float4 qr[32];
    {
        const float4* qp = (const float4*)(q + qbase + (size_t)tid * R_);
#pragma unroll
        for (int i = 0; i < 32; i++) {
            float4 t = qp[i];
            qr[i] = make_float4(t.x * scale, t.y * scale, t.z * scale, t.w * scale);
        }
    }
    {
        float4 z = make_float4(0.f, 0.f, 0.f, 0.f);
        float4* Or4 = (float4*)(O_s + tid * 132);
#pragma unroll
        for (int d4 = 0; d4 < 32; d4++) Or4[d4] = z;
    }
    __syncthreads();

    const int t = t0 + tid;
    float m = -1e30f, l = 0.f;

    int s_lo = t0 - W;
    if (s_lo < 0) s_lo = 0;
    const int s_start = s_lo & ~31;

    for (int s0 = s_start; s0 < t0 + 64; s0 += 32) {
        {
            const float4* kp = (const float4*)(k + ((size_t)b * T_ + s0) * R_);
            const float4* vp = (const float4*)(v + ((size_t)b * T_ + s0) * R_);
            float4* ks4 = (float4*)k_s;
            float4* vs4 = (float4*)v_s;
#pragma unroll
            for (int i = 0; i < 16; i++) {
                ks4[tid + i * 64] = kp[tid + i * 64];
                vs4[tid + i * 64] = vp[tid + i * 64];
            }
        }
        __syncthreads();

        float p[32];
        float mt = m;
#pragma unroll 4
        for (int j = 0; j < 32; j++) {
            const float4* kr = (const float4*)(k_s + j * 128);
            float4 s4 = make_float4(0.f, 0.f, 0.f, 0.f);
#pragma unroll
            for (int d4 = 0; d4 < 32; d4++) {
                float4 kv = kr[d4];
                s4.x += qr[d4].x * kv.x;
                s4.y += qr[d4].y * kv.y;
                s4.z += qr[d4].z * kv.z;
                s4.w += qr[d4].w * kv.w;
            }
            float s = (s4.x + s4.y) + (s4.z + s4.w);
            const int sidx = s0 + j;
            if (sidx > t || (t - sidx) > W) s = -1e30f;
            p[j] = s;
            mt = fmaxf(mt, s);
        }

        const float alpha = expf(m - mt);
        m = mt;
        float lt = 0.f;
#pragma unroll
        for (int j = 0; j < 32; j++) {
            const float pv = (p[j] > -1e29f) ? expf(p[j] - mt) : 0.f;
            p[j] = pv;
            lt += pv;
        }
        l = l * alpha + lt;

        float4* Or4 = (float4*)(O_s + tid * 132);
        const float4* vs4 = (const float4*)v_s;
#pragma unroll 2
        for (int d4 = 0; d4 < 32; d4++) {
            float4 acc = Or4[d4];
            acc.x *= alpha; acc.y *= alpha; acc.z *= alpha; acc.w *= alpha;
#pragma unroll
            for (int j = 0; j < 32; j++) {
                float4 vv = vs4[j * 32 + d4];
                acc.x += p[j] * vv.x;
                acc.y += p[j] * vv.y;
                acc.z += p[j] * vv.z;
                acc.w += p[j] * vv.w;
            }
            Or4[d4] = acc;
        }
        __syncthreads();
    }

    const float inv_l = 1.f / l;
    float4* yo = (float4*)(y + qbase + (size_t)tid * R_);
    const float4* Or4 = (const float4*)(O_s + tid * 132);
#pragma unroll
    for (int d4 = 0; d4 < 32; d4++) {
        float4 o = Or4[d4];
        yo[d4] = make_float4(tf32f(o.x * inv_l), tf32f(o.y * inv_l),
                             tf32f(o.z * inv_l), tf32f(o.w * inv_l));
    }
}

// ---------------------------------------------------------------------------
// Host launcher
// ---------------------------------------------------------------------------
extern "C" void kernel_launch(void* const* d_in, const int* in_sizes, int n_in,
                              void* d_out, int out_size) {
    const float* x    = (const float*)d_in[0];
    const float* Uq   = (const float*)d_in[1];
    const float* Uk   = (const float*)d_in[2];
    const float* Uv   = (const float*)d_in[3];
    const float* cosp = (const float*)d_in[4];
    const float* sinp = (const float*)d_in[5];
    const float* ln1w = (const float*)d_in[6];
    const float* ln2w = (const float*)d_in[7];
    const float* Wo   = (const float*)d_in[8];
    const float* w1   = (const float*)d_in[9];
    const float* w3   = (const float*)d_in[10];
    const float* w2   = (const float*)d_in[11];
    const int*   win  = (const int*)d_in[12];
    float* out = (float*)d_out;

    float *normed, *q, *k, *v, *y, *h, *t1;
    float *wq, *wk, *wv, *wo, *w1r, *w3r, *w2r;
    cudaGetSymbolAddress((void**)&normed, g_normed);
    cudaGetSymbolAddress((void**)&q, g_q);
    cudaGetSymbolAddress((void**)&k, g_k);
    cudaGetSymbolAddress((void**)&v, g_v);
    cudaGetSymbolAddress((void**)&y, g_y);
    cudaGetSymbolAddress((void**)&h, g_h);
    cudaGetSymbolAddress((void**)&t1, g_t1);
    cudaGetSymbolAddress((void**)&wq, g_wq);
    cudaGetSymbolAddress((void**)&wk, g_wk);
    cudaGetSymbolAddress((void**)&wv, g_wv);
    cudaGetSymbolAddress((void**)&wo, g_wo);
    cudaGetSymbolAddress((void**)&w1r, g_w1);
    cudaGetSymbolAddress((void**)&w3r, g_w3);
    cudaGetSymbolAddress((void**)&w2r, g_w2);

    cudaFuncSetAttribute(attn_kernel, cudaFuncAttributeMaxDynamicSharedMemorySize,
                         ATTN_SMEM_BYTES);
    cudaFuncSetAttribute(tfgemm_kernel<0>, cudaFuncAttributeMaxDynamicSharedMemorySize,
                         GEMM_SMEM_BYTES);
    cudaFuncSetAttribute(tfgemm_kernel<1>, cudaFuncAttributeMaxDynamicSharedMemorySize,
                         GEMM_SMEM_BYTES);
    cudaFuncSetAttribute(tfgemm_kernel<2>, cudaFuncAttributeMaxDynamicSharedMemorySize,
                         GEMM_SMEM_BYTES);
    cudaFuncSetAttribute(qkv_kernel, cudaFuncAttributeMaxDynamicSharedMemorySize,
                         GEMM_SMEM_BYTES);

    // weight prep (tf32 rounding)
    const int nSmall = R_ * D_ / 4;
    const int nBig   = DFF_ * D_ / 4;
    round4_kernel<<<(nSmall + 255) / 256, 256>>>((const float4*)Uq, (float4*)wq, nSmall);
    round4_kernel<<<(nSmall + 255) / 256, 256>>>((const float4*)Uk, (float4*)wk, nSmall);
    round4_kernel<<<(nSmall + 255) / 256, 256>>>((const float4*)Uv, (float4*)wv, nSmall);
    round4_kernel<<<(nSmall + 255) / 256, 256>>>((const float4*)Wo, (float4*)wo, nSmall);
    round4_kernel<<<(nBig + 255) / 256, 256>>>((const float4*)w1, (float4*)w1r, nBig);
    round4_kernel<<<(nBig + 255) / 256, 256>>>((const float4*)w3, (float4*)w3r, nBig);
    round4_kernel<<<(nBig + 255) / 256, 256>>>((const float4*)w2, (float4*)w2r, nBig);

    // 1) normed = tf32(rmsnorm(x, ln1_w))
    rmsnorm_kernel<<<BT_, 256>>>(x, ln1w, normed);

    // 2) fused q,k,v projections
    qkv_kernel<<<dim3(3, BT_ / 128), 256, GEMM_SMEM_BYTES>>>(normed, wq, wk, wv, q, k, v, BT_, D_);

    // 3) RoPE
    rope_kernel<<<BT_, 64>>>(q, k, cosp, sinp);

    // 4) attention -> y (tf32-rounded)
    attn_kernel<<<dim3(T_ / 64, B_), 64, ATTN_SMEM_BYTES>>>(q, k, v, y, win);

    // 5) out = x + y @ Wo^T
    tfgemm_kernel<1><<<dim3(D_ / 128, BT_ / 128), 256, GEMM_SMEM_BYTES>>>(y, wo, x, out, BT_, D_, R_);

    // 6) h = tf32(rmsnorm(out, ln2_w))
    rmsnorm_kernel<<<BT_, 256>>>(out, ln2w, h);

    // 7) t1 = h @ w1^T
    tfgemm_kernel<0><<<dim3(DFF_ / 128, BT_ / 128), 256, GEMM_SMEM_BYTES>>>(h, w1r, nullptr, t1, BT_, DFF_, D_);

    // 8) t1 = tf32(t1 * silu(h @ w3^T))
    tfgemm_kernel<2><<<dim3(DFF_ / 128, BT_ / 128), 256, GEMM_SMEM_BYTES>>>(h, w3r, t1, t1, BT_, DFF_, D_);

    // 9) out = out + t1 @ w2^T
    tfgemm_kernel<1><<<dim3(D_ / 128, BT_ / 128), 256, GEMM_SMEM_BYTES>>>(t1, w2r, out, out, BT_, D_, DFF_);
}